// round 1
// baseline (speedup 1.0000x reference)
#include <cuda_runtime.h>
#include <cstdint>
#include <math.h>

#define BB 2
#define NN 512
#define CC 256
#define HH 256
#define WW 256
#define HWP 65536
#define POOLN 7
#define DIN 12544
#define OUTD 1024
#define NROI 1024
#define NCLS 11

// Scratch (device globals; allocation-free per harness rules)
__device__ float g_featT[(size_t)BB * HWP * CC];   // NHWC feat, 134 MB
__device__ float g_x[(size_t)NROI * DIN];          // pooled features, bin-major
__device__ float g_h1[(size_t)NROI * OUTD];
__device__ float g_h2[(size_t)NROI * OUTD];

// ---------------------------------------------------------------------------
// NCHW -> NHWC transpose (per batch: (C, HW) -> (HW, C)), 32x32 smem tiles
// ---------------------------------------------------------------------------
__global__ void transpose_kernel(const float* __restrict__ feat) {
    __shared__ float tile[32][33];
    int b  = blockIdx.z;
    int p0 = blockIdx.x * 32;   // pixel tile
    int c0 = blockIdx.y * 32;   // channel tile
    const float* in = feat + (size_t)b * CC * HWP;
    float* out      = g_featT + (size_t)b * HWP * CC;
    int tx = threadIdx.x, ty = threadIdx.y;
#pragma unroll
    for (int i = 0; i < 32; i += 8)
        tile[ty + i][tx] = in[(size_t)(c0 + ty + i) * HWP + p0 + tx];
    __syncthreads();
#pragma unroll
    for (int i = 0; i < 32; i += 8)
        out[(size_t)(p0 + ty + i) * CC + c0 + tx] = tile[tx][ty + i];
}

// ---------------------------------------------------------------------------
// Rotated ROI align. One block per ROI, one thread per channel.
// Writes g_x[r][bin*256 + c]  (bin = ph*7+pw), i.e. bin-major layout.
// ---------------------------------------------------------------------------
__global__ void roi_kernel(const float* __restrict__ proposals) {
    int r = blockIdx.x;          // 0..1023
    int b = r >> 9;
    int c = threadIdx.x;         // channel
    const float* pr = proposals + r * 5;
    float cx = pr[0], cy = pr[1], w = pr[2], h = pr[3], th = pr[4];
    float cs = cosf(th), sn = sinf(th);
    const float* fb = g_featT + (size_t)b * HWP * CC;
    float* xo = g_x + (size_t)r * DIN;

    float hstep = h / (float)POOLN;
    float wstep = w / (float)POOLN;

    for (int bin = 0; bin < 49; ++bin) {
        int ph = bin / 7, pw = bin % 7;
        float acc = 0.f;
#pragma unroll
        for (int s = 0; s < 4; ++s) {
            int sy = s >> 1, sx = s & 1;
            float yl = -h * 0.5f + hstep * ((float)ph + ((float)sy + 0.5f) * 0.5f);
            float xl = -w * 0.5f + wstep * ((float)pw + ((float)sx + 0.5f) * 0.5f);
            float gx = cx + xl * cs - yl * sn;
            float gy = cy + xl * sn + yl * cs;
            if (gy > -1.f && gy < (float)HH && gx > -1.f && gx < (float)WW) {
                float y = fminf(fmaxf(gy, 0.f), 255.f);
                float x = fminf(fmaxf(gx, 0.f), 255.f);
                float y0f = floorf(y), x0f = floorf(x);
                int y0 = (int)y0f, x0 = (int)x0f;
                int y1 = min(y0 + 1, 255), x1 = min(x0 + 1, 255);
                float ly = y - y0f, lx = x - x0f;
                float hy = 1.f - ly, hx = 1.f - lx;
                float f00 = fb[((size_t)y0 * WW + x0) * CC + c];
                float f01 = fb[((size_t)y0 * WW + x1) * CC + c];
                float f10 = fb[((size_t)y1 * WW + x0) * CC + c];
                float f11 = fb[((size_t)y1 * WW + x1) * CC + c];
                acc += hy * hx * f00 + hy * lx * f01 + ly * hx * f10 + ly * lx * f11;
            }
        }
        xo[bin * CC + c] = acc * 0.25f;
    }
}

// ---------------------------------------------------------------------------
// Fused GEMM + bias + relu.  C[M=1024, N=1024] = relu(A[M,K] @ Bw[K,N] + bias)
// STAGE 1: A=g_x (bin-major), Bw=W1 with k -> (k%256)*49 + k/256 row permute.
// STAGE 2: A=g_h1, Bw=W2 identity.
// BM=128, BN=64, BK=16, 256 threads, 8x4 per-thread tile, reg prefetch.
// ---------------------------------------------------------------------------
template <int STAGE>
__global__ void __launch_bounds__(256)
gemm_bias_relu(const float* __restrict__ Bw, const float* __restrict__ bias, int K) {
    const int N = 1024;
    const float* A = (STAGE == 1) ? g_x : g_h1;
    float* C       = (STAGE == 1) ? g_h1 : g_h2;
    constexpr bool PERM = (STAGE == 1);

    __shared__ float As[16][128];
    __shared__ float Bs[16][64];

    int tid = threadIdx.x;
    int tx = tid & 15, ty = tid >> 4;
    int bm = blockIdx.y * 128, bn = blockIdx.x * 64;

    int am  = tid >> 2;          // A tile row (0..63, +64 for second half)
    int akq = (tid & 3) * 4;     // A k quad
    int bkr = tid >> 4;          // B tile k row (0..15)
    int bnq = (tid & 15) * 4;    // B n quad

    float acc[8][4];
#pragma unroll
    for (int i = 0; i < 8; i++)
#pragma unroll
        for (int j = 0; j < 4; j++) acc[i][j] = 0.f;

    float4 pa0, pa1, pb;
    const int numTiles = K / 16;

    // prefetch tile 0
    pa0 = *(const float4*)&A[(size_t)(bm + am) * K + akq];
    pa1 = *(const float4*)&A[(size_t)(bm + am + 64) * K + akq];
    {
        int krow = bkr;
        int prow = PERM ? ((krow & 255) * 49 + (krow >> 8)) : krow;
        pb = *(const float4*)&Bw[(size_t)prow * N + bn + bnq];
    }

    for (int t = 0; t < numTiles; ++t) {
        As[akq + 0][am] = pa0.x; As[akq + 1][am] = pa0.y;
        As[akq + 2][am] = pa0.z; As[akq + 3][am] = pa0.w;
        As[akq + 0][am + 64] = pa1.x; As[akq + 1][am + 64] = pa1.y;
        As[akq + 2][am + 64] = pa1.z; As[akq + 3][am + 64] = pa1.w;
        *(float4*)&Bs[bkr][bnq] = pb;
        __syncthreads();

        if (t + 1 < numTiles) {
            int k0 = (t + 1) * 16;
            pa0 = *(const float4*)&A[(size_t)(bm + am) * K + k0 + akq];
            pa1 = *(const float4*)&A[(size_t)(bm + am + 64) * K + k0 + akq];
            int krow = k0 + bkr;
            int prow = PERM ? ((krow & 255) * 49 + (krow >> 8)) : krow;
            pb = *(const float4*)&Bw[(size_t)prow * N + bn + bnq];
        }

#pragma unroll
        for (int kk = 0; kk < 16; ++kk) {
            float4 a0 = *(const float4*)&As[kk][ty * 8];
            float4 a1 = *(const float4*)&As[kk][ty * 8 + 4];
            float4 bb = *(const float4*)&Bs[kk][tx * 4];
            float a[8] = {a0.x, a0.y, a0.z, a0.w, a1.x, a1.y, a1.z, a1.w};
            float bv[4] = {bb.x, bb.y, bb.z, bb.w};
#pragma unroll
            for (int i = 0; i < 8; i++)
#pragma unroll
                for (int j = 0; j < 4; j++) acc[i][j] += a[i] * bv[j];
        }
        __syncthreads();
    }

    float4 bvq = *(const float4*)&bias[bn + tx * 4];
    float bvv[4] = {bvq.x, bvq.y, bvq.z, bvq.w};
#pragma unroll
    for (int i = 0; i < 8; i++) {
        float4 o;
        o.x = fmaxf(acc[i][0] + bvv[0], 0.f);
        o.y = fmaxf(acc[i][1] + bvv[1], 0.f);
        o.z = fmaxf(acc[i][2] + bvv[2], 0.f);
        o.w = fmaxf(acc[i][3] + bvv[3], 0.f);
        *(float4*)&C[(size_t)(bm + ty * 8 + i) * N + bn + tx * 4] = o;
    }
}

// ---------------------------------------------------------------------------
// Head: cls (11) + reg (5) GEMV per ROI + box decode.
// Output layout: boxes [0, 5120), cls [5120, 16384)
// ---------------------------------------------------------------------------
__global__ void head_kernel(const float* __restrict__ proposals,
                            const float* __restrict__ Wcls, const float* __restrict__ bcls,
                            const float* __restrict__ Wreg, const float* __restrict__ breg,
                            float* __restrict__ out) {
    int r = blockIdx.x;
    int tid = threadIdx.x;
    int j = tid >> 4, lane = tid & 15;   // 16 outputs x 16 lanes
    __shared__ float sred[16];
    const float* hrow = g_h2 + (size_t)r * OUTD;

    float s = 0.f;
    if (j < 11) {
        for (int k = lane; k < OUTD; k += 16) s += hrow[k] * Wcls[k * 11 + j];
    } else {
        int jj = j - 11;
        for (int k = lane; k < OUTD; k += 16) s += hrow[k] * Wreg[k * 5 + jj];
    }
#pragma unroll
    for (int off = 8; off; off >>= 1) s += __shfl_down_sync(0xffffffffu, s, off, 16);
    if (lane == 0) {
        float bb = (j < 11) ? bcls[j] : breg[j - 11];
        sred[j] = s + bb;
    }
    __syncthreads();

    if (tid < 11) out[NROI * 5 + r * 11 + tid] = sred[tid];
    if (tid == 0) {
        const float* pr = proposals + r * 5;
        float p0 = pr[0] * 4.f, p1 = pr[1] * 4.f;
        float p2 = pr[2] * 4.f, p3 = pr[3] * 4.f, p4 = pr[4];
        float r0 = sred[11], r1 = sred[12], r2 = sred[13], r3 = sred[14], r4 = sred[15];
        const float CLV = 4.1351665567423560f;     // |log(16/1000)|
        const float PI  = 3.14159265358979323846f;
        float bx = p2 * r0 + p0;
        float by = p3 * r1 + p1;
        float bw = p2 * expf(fminf(fmaxf(r2, -CLV), CLV));
        float bh = p3 * expf(fminf(fmaxf(r3, -CLV), CLV));
        float a2 = p4 + r4 + PI * 0.5f;
        float m  = a2 - floorf(a2 / PI) * PI;      // python-mod semantics, [0, pi)
        float ba = m - PI * 0.5f;
        float* ob = out + r * 5;
        ob[0] = bx; ob[1] = by; ob[2] = bw; ob[3] = bh; ob[4] = ba;
    }
}

extern "C" void kernel_launch(void* const* d_in, const int* in_sizes, int n_in,
                              void* d_out, int out_size) {
    const float* feat      = (const float*)d_in[0];
    const float* proposals = (const float*)d_in[1];
    const float* W1   = (const float*)d_in[2];
    const float* b1   = (const float*)d_in[3];
    const float* W2   = (const float*)d_in[4];
    const float* b2   = (const float*)d_in[5];
    const float* Wcls = (const float*)d_in[6];
    const float* bcls = (const float*)d_in[7];
    const float* Wreg = (const float*)d_in[8];
    const float* breg = (const float*)d_in[9];
    float* out = (float*)d_out;

    transpose_kernel<<<dim3(HWP / 32, CC / 32, BB), dim3(32, 8)>>>(feat);
    roi_kernel<<<NROI, 256>>>(proposals);
    gemm_bias_relu<1><<<dim3(16, 8), 256>>>(W1, b1, DIN);   // x @ W1 -> h1
    gemm_bias_relu<2><<<dim3(16, 8), 256>>>(W2, b2, OUTD);  // h1 @ W2 -> h2
    head_kernel<<<NROI, 256>>>(proposals, Wcls, bcls, Wreg, breg, out);
}

// round 2
// speedup vs baseline: 1.7687x; 1.7687x over previous
#include <cuda_runtime.h>
#include <cstdint>
#include <math.h>

#define BB 2
#define NN 512
#define CC 256
#define HH 256
#define WW 256
#define HWP 65536
#define POOLN 7
#define DIN 12544
#define OUTD 1024
#define NROI 1024
#define NCLS 11

// Scratch (device globals; allocation-free per harness rules)
__device__ float g_featT[(size_t)BB * HWP * CC];   // NHWC feat, 134 MB
__device__ float g_x[(size_t)NROI * DIN];          // pooled features, bin-major
__device__ float g_h1[(size_t)NROI * OUTD];
__device__ float g_h2[(size_t)NROI * OUTD];

// ---------------------------------------------------------------------------
// NCHW -> NHWC transpose (per batch: (C, HW) -> (HW, C)), 32x32 smem tiles
// ---------------------------------------------------------------------------
__global__ void transpose_kernel(const float* __restrict__ feat) {
    __shared__ float tile[32][33];
    int b  = blockIdx.z;
    int p0 = blockIdx.x * 32;   // pixel tile
    int c0 = blockIdx.y * 32;   // channel tile
    const float* in = feat + (size_t)b * CC * HWP;
    float* out      = g_featT + (size_t)b * HWP * CC;
    int tx = threadIdx.x, ty = threadIdx.y;
#pragma unroll
    for (int i = 0; i < 32; i += 8)
        tile[ty + i][tx] = in[(size_t)(c0 + ty + i) * HWP + p0 + tx];
    __syncthreads();
#pragma unroll
    for (int i = 0; i < 32; i += 8)
        out[(size_t)(p0 + ty + i) * CC + c0 + tx] = tile[tx][ty + i];
}

// ---------------------------------------------------------------------------
// Rotated ROI align. One block per ROI, one thread per channel.
// Writes g_x[r][bin*256 + c]  (bin = ph*7+pw), i.e. bin-major layout.
// ---------------------------------------------------------------------------
__global__ void roi_kernel(const float* __restrict__ proposals) {
    int r = blockIdx.x;          // 0..1023
    int b = r >> 9;
    int c = threadIdx.x;         // channel
    const float* pr = proposals + r * 5;
    float cx = pr[0], cy = pr[1], w = pr[2], h = pr[3], th = pr[4];
    float cs = cosf(th), sn = sinf(th);
    const float* fb = g_featT + (size_t)b * HWP * CC;
    float* xo = g_x + (size_t)r * DIN;

    float hstep = h / (float)POOLN;
    float wstep = w / (float)POOLN;

    for (int bin = 0; bin < 49; ++bin) {
        int ph = bin / 7, pw = bin % 7;
        float acc = 0.f;
#pragma unroll
        for (int s = 0; s < 4; ++s) {
            int sy = s >> 1, sx = s & 1;
            float yl = -h * 0.5f + hstep * ((float)ph + ((float)sy + 0.5f) * 0.5f);
            float xl = -w * 0.5f + wstep * ((float)pw + ((float)sx + 0.5f) * 0.5f);
            float gx = cx + xl * cs - yl * sn;
            float gy = cy + xl * sn + yl * cs;
            if (gy > -1.f && gy < (float)HH && gx > -1.f && gx < (float)WW) {
                float y = fminf(fmaxf(gy, 0.f), 255.f);
                float x = fminf(fmaxf(gx, 0.f), 255.f);
                float y0f = floorf(y), x0f = floorf(x);
                int y0 = (int)y0f, x0 = (int)x0f;
                int y1 = min(y0 + 1, 255), x1 = min(x0 + 1, 255);
                float ly = y - y0f, lx = x - x0f;
                float hy = 1.f - ly, hx = 1.f - lx;
                float f00 = fb[((size_t)y0 * WW + x0) * CC + c];
                float f01 = fb[((size_t)y0 * WW + x1) * CC + c];
                float f10 = fb[((size_t)y1 * WW + x0) * CC + c];
                float f11 = fb[((size_t)y1 * WW + x1) * CC + c];
                acc += hy * hx * f00 + hy * lx * f01 + ly * hx * f10 + ly * lx * f11;
            }
        }
        xo[bin * CC + c] = acc * 0.25f;
    }
}

// ---------------------------------------------------------------------------
// TF32 tensor-core GEMM + bias + relu.
// C[M=1024, N=1024] = relu(A[M,K] @ Bw[K,N] + bias)
// STAGE 1: A=g_x, Bw=W1 with k -> (k%256)*49 + k/256 row permute, K=12544.
// STAGE 2: A=g_h1, Bw=W2 identity, K=1024.
// BM=128, BN=64, BK=32, 256 threads (8 warps as 4x2), warp tile 32x32,
// mma.sync.m16n8k8.tf32, register-prefetch single-buffer smem.
// ---------------------------------------------------------------------------
__device__ __forceinline__ uint32_t f2tf(float f) {
    uint32_t u;
    asm("cvt.rna.tf32.f32 %0, %1;" : "=r"(u) : "f"(f));
    return u;
}

__device__ __forceinline__ void mma_tf32(float c[4], const uint32_t a[4], const uint32_t b[2]) {
    asm volatile(
        "mma.sync.aligned.m16n8k8.row.col.f32.tf32.tf32.f32 "
        "{%0,%1,%2,%3},{%4,%5,%6,%7},{%8,%9},{%0,%1,%2,%3};"
        : "+f"(c[0]), "+f"(c[1]), "+f"(c[2]), "+f"(c[3])
        : "r"(a[0]), "r"(a[1]), "r"(a[2]), "r"(a[3]), "r"(b[0]), "r"(b[1]));
}

#define SA 136   // 136 % 32 == 8 -> conflict-free fragment loads
#define SB 72    // 72 % 32 == 8

template <int STAGE>
__global__ void __launch_bounds__(256)
gemm_tc(const float* __restrict__ Bw, const float* __restrict__ bias, int K) {
    const int N = 1024;
    const float* A = (STAGE == 1) ? g_x : g_h1;
    float* C       = (STAGE == 1) ? g_h1 : g_h2;
    constexpr bool PERM = (STAGE == 1);

    __shared__ uint32_t As[32][SA];   // [k][m]
    __shared__ uint32_t Bs[32][SB];   // [k][n]

    int tid = threadIdx.x;
    int bm = blockIdx.y * 128, bn = blockIdx.x * 64;

    // producer mapping
    int amr = tid >> 1;              // A row 0..127
    int akq = (tid & 1) * 16;        // A k half
    int bkr = tid >> 3;              // B k row 0..31
    int bn0 = (tid & 7) * 8;         // B n start

    // consumer mapping
    int warpId = tid >> 5;
    int lane = tid & 31;
    int wm = warpId >> 1;            // 0..3
    int wn = warpId & 1;             // 0..1
    int g = lane >> 2, tig = lane & 3;

    float acc[2][4][4];
#pragma unroll
    for (int mt = 0; mt < 2; mt++)
#pragma unroll
        for (int nt = 0; nt < 4; nt++)
#pragma unroll
            for (int i = 0; i < 4; i++) acc[mt][nt][i] = 0.f;

    const int numTiles = K / 32;
    float4 pa[4], pb[2];

    // prefetch tile 0
    {
        const float* arow = A + (size_t)(bm + amr) * K + akq;
#pragma unroll
        for (int j = 0; j < 4; j++) pa[j] = *(const float4*)(arow + 4 * j);
        int gk = bkr;
        int prow = PERM ? ((gk & 255) * 49 + (gk >> 8)) : gk;
        const float* brow = Bw + (size_t)prow * N + bn + bn0;
        pb[0] = *(const float4*)(brow);
        pb[1] = *(const float4*)(brow + 4);
    }

    for (int t = 0; t < numTiles; ++t) {
        // store prefetched tile (with tf32 convert)
#pragma unroll
        for (int j = 0; j < 4; j++) {
            int kk = akq + 4 * j;
            As[kk + 0][amr] = f2tf(pa[j].x);
            As[kk + 1][amr] = f2tf(pa[j].y);
            As[kk + 2][amr] = f2tf(pa[j].z);
            As[kk + 3][amr] = f2tf(pa[j].w);
        }
        {
            uint4 v0 = make_uint4(f2tf(pb[0].x), f2tf(pb[0].y), f2tf(pb[0].z), f2tf(pb[0].w));
            uint4 v1 = make_uint4(f2tf(pb[1].x), f2tf(pb[1].y), f2tf(pb[1].z), f2tf(pb[1].w));
            *(uint4*)&Bs[bkr][bn0] = v0;
            *(uint4*)&Bs[bkr][bn0 + 4] = v1;
        }
        __syncthreads();

        // prefetch next tile
        if (t + 1 < numTiles) {
            int k0 = (t + 1) * 32;
            const float* arow = A + (size_t)(bm + amr) * K + k0 + akq;
#pragma unroll
            for (int j = 0; j < 4; j++) pa[j] = *(const float4*)(arow + 4 * j);
            int gk = k0 + bkr;
            int prow = PERM ? ((gk & 255) * 49 + (gk >> 8)) : gk;
            const float* brow = Bw + (size_t)prow * N + bn + bn0;
            pb[0] = *(const float4*)(brow);
            pb[1] = *(const float4*)(brow + 4);
        }

        // compute: 4 k-steps of m16n8k8
#pragma unroll
        for (int ks = 0; ks < 4; ks++) {
            int kb = ks * 8;
            uint32_t afr[2][4], bfr[4][2];
#pragma unroll
            for (int mt = 0; mt < 2; mt++) {
                int m0 = wm * 32 + mt * 16;
                afr[mt][0] = As[kb + tig][m0 + g];
                afr[mt][1] = As[kb + tig][m0 + 8 + g];
                afr[mt][2] = As[kb + tig + 4][m0 + g];
                afr[mt][3] = As[kb + tig + 4][m0 + 8 + g];
            }
#pragma unroll
            for (int nt = 0; nt < 4; nt++) {
                int n0 = wn * 32 + nt * 8;
                bfr[nt][0] = Bs[kb + tig][n0 + g];
                bfr[nt][1] = Bs[kb + tig + 4][n0 + g];
            }
#pragma unroll
            for (int mt = 0; mt < 2; mt++)
#pragma unroll
                for (int nt = 0; nt < 4; nt++)
                    mma_tf32(acc[mt][nt], afr[mt], bfr[nt]);
        }
        __syncthreads();
    }

    // epilogue: bias + relu, float2 stores
#pragma unroll
    for (int mt = 0; mt < 2; mt++) {
        int r0 = bm + wm * 32 + mt * 16 + g;
        int r1 = r0 + 8;
#pragma unroll
        for (int nt = 0; nt < 4; nt++) {
            int cb = bn + wn * 32 + nt * 8 + tig * 2;
            float2 bv = *(const float2*)&bias[cb];
            float2 o0, o1;
            o0.x = fmaxf(acc[mt][nt][0] + bv.x, 0.f);
            o0.y = fmaxf(acc[mt][nt][1] + bv.y, 0.f);
            o1.x = fmaxf(acc[mt][nt][2] + bv.x, 0.f);
            o1.y = fmaxf(acc[mt][nt][3] + bv.y, 0.f);
            *(float2*)&C[(size_t)r0 * N + cb] = o0;
            *(float2*)&C[(size_t)r1 * N + cb] = o1;
        }
    }
}

// ---------------------------------------------------------------------------
// Head: cls (11) + reg (5) GEMV per ROI + box decode.
// Output layout: boxes [0, 5120), cls [5120, 16384)
// ---------------------------------------------------------------------------
__global__ void head_kernel(const float* __restrict__ proposals,
                            const float* __restrict__ Wcls, const float* __restrict__ bcls,
                            const float* __restrict__ Wreg, const float* __restrict__ breg,
                            float* __restrict__ out) {
    int r = blockIdx.x;
    int tid = threadIdx.x;
    int j = tid >> 4, lane = tid & 15;   // 16 outputs x 16 lanes
    __shared__ float sred[16];
    const float* hrow = g_h2 + (size_t)r * OUTD;

    float s = 0.f;
    if (j < 11) {
        for (int k = lane; k < OUTD; k += 16) s += hrow[k] * Wcls[k * 11 + j];
    } else {
        int jj = j - 11;
        for (int k = lane; k < OUTD; k += 16) s += hrow[k] * Wreg[k * 5 + jj];
    }
#pragma unroll
    for (int off = 8; off; off >>= 1) s += __shfl_down_sync(0xffffffffu, s, off, 16);
    if (lane == 0) {
        float bb = (j < 11) ? bcls[j] : breg[j - 11];
        sred[j] = s + bb;
    }
    __syncthreads();

    if (tid < 11) out[NROI * 5 + r * 11 + tid] = sred[tid];
    if (tid == 0) {
        const float* pr = proposals + r * 5;
        float p0 = pr[0] * 4.f, p1 = pr[1] * 4.f;
        float p2 = pr[2] * 4.f, p3 = pr[3] * 4.f, p4 = pr[4];
        float r0 = sred[11], r1 = sred[12], r2 = sred[13], r3 = sred[14], r4 = sred[15];
        const float CLV = 4.1351665567423560f;     // |log(16/1000)|
        const float PI  = 3.14159265358979323846f;
        float bx = p2 * r0 + p0;
        float by = p3 * r1 + p1;
        float bw = p2 * expf(fminf(fmaxf(r2, -CLV), CLV));
        float bh = p3 * expf(fminf(fmaxf(r3, -CLV), CLV));
        float a2 = p4 + r4 + PI * 0.5f;
        float m  = a2 - floorf(a2 / PI) * PI;      // python-mod semantics, [0, pi)
        float ba = m - PI * 0.5f;
        float* ob = out + r * 5;
        ob[0] = bx; ob[1] = by; ob[2] = bw; ob[3] = bh; ob[4] = ba;
    }
}

extern "C" void kernel_launch(void* const* d_in, const int* in_sizes, int n_in,
                              void* d_out, int out_size) {
    const float* feat      = (const float*)d_in[0];
    const float* proposals = (const float*)d_in[1];
    const float* W1   = (const float*)d_in[2];
    const float* b1   = (const float*)d_in[3];
    const float* W2   = (const float*)d_in[4];
    const float* b2   = (const float*)d_in[5];
    const float* Wcls = (const float*)d_in[6];
    const float* bcls = (const float*)d_in[7];
    const float* Wreg = (const float*)d_in[8];
    const float* breg = (const float*)d_in[9];
    float* out = (float*)d_out;

    transpose_kernel<<<dim3(HWP / 32, CC / 32, BB), dim3(32, 8)>>>(feat);
    roi_kernel<<<NROI, 256>>>(proposals);
    gemm_tc<1><<<dim3(16, 8), 256>>>(W1, b1, DIN);   // x @ W1 -> h1
    gemm_tc<2><<<dim3(16, 8), 256>>>(W2, b2, OUTD);  // h1 @ W2 -> h2
    head_kernel<<<NROI, 256>>>(proposals, Wcls, bcls, Wreg, breg, out);
}